// round 16
// baseline (speedup 1.0000x reference)
#include <cuda_runtime.h>
#include <cuda_bf16.h>
#include <cstdint>

#define BB   2
#define CC   256
#define NN   2304
#define OC3  768
#define NH   8
#define HD   32
#define NBH  (BB*NH)
#define NG   (BB*NN)     // 4608 flattened (b,n)
#define NSPLIT 2
#define KT_PER_SPLIT 18  // 36 k-tiles / 2 splits

// Pair-permuted layouts: within each 8-word group, original word g maps to
// position (g<4 ? 2g : 2(g-4)+1), so b-fragment pairs (g, g+4) are adjacent.
__device__ __align__(16) uint32_t g_QPh[NBH * NN * (HD/2)];  // Q bf16 (pre-scaled) [bh][n][16] permuted
__device__ __align__(16) uint32_t g_XPh[NG * 128];           // X bf16 pairs along c [ng][c/2]
__device__ __align__(16) uint32_t g_WqPh[OC3 * 128];         // W_qkv split [o][c/2]
__device__ __align__(16) uint32_t g_WqPl[OC3 * 128];
__device__ __align__(16) uint32_t g_WpPh[CC * 128];          // W_proj split [c][c'/2]
__device__ __align__(16) uint32_t g_WpPl[CC * 128];
__device__ __align__(16) uint32_t g_KPh[NBH * NN * (HD/2)];  // K bf16 [bh][n][16] permuted
__device__ __align__(16) uint32_t g_VPh[NBH * HD * (NN/2)];  // V^T fp16 [bh][d][n/2] permuted
__device__ __align__(16) float    g_OPf[NSPLIT * NG * CC];   // attn partial O (unnormalized fp32)
__device__ __align__(16) float    g_Lp [NSPLIT * NBH * NN];  // attn partial l
__device__ __align__(16) uint32_t g_OPh[NG * 128];           // attn out bf16 [ng][c/2]

// ---------------- helpers ----------------
__device__ __forceinline__ uint32_t bf2_pack(float lo_elem, float hi_elem) {
    uint32_t d;
    asm("cvt.rn.bf16x2.f32 %0, %1, %2;" : "=r"(d) : "f"(hi_elem), "f"(lo_elem));
    return d;
}
__device__ __forceinline__ uint32_t f16x2_pack(float lo_elem, float hi_elem) {
    uint32_t d;
    asm("cvt.rn.f16x2.f32 %0, %1, %2;" : "=r"(d) : "f"(hi_elem), "f"(lo_elem));
    return d;
}
__device__ __forceinline__ uint32_t ex2_f16x2(uint32_t v) {
    uint32_t r;
    asm("ex2.approx.f16x2 %0, %1;" : "=r"(r) : "r"(v));
    return r;
}
__device__ __forceinline__ float2 bf2_unpack(uint32_t v) {
    __nv_bfloat162 h;
    *reinterpret_cast<uint32_t*>(&h) = v;
    return __bfloat1622float2(h);
}
__device__ __forceinline__ void split2(float x, float y, uint32_t& hi, uint32_t& lo) {
    hi = bf2_pack(x, y);
    float2 f = bf2_unpack(hi);
    lo = bf2_pack(x - f.x, y - f.y);
}
__device__ __forceinline__ void mma16816(float c[4], const uint32_t a[4], uint32_t b0, uint32_t b1) {
    asm volatile(
        "mma.sync.aligned.m16n8k16.row.col.f32.bf16.bf16.f32 "
        "{%0,%1,%2,%3}, {%4,%5,%6,%7}, {%8,%9}, {%0,%1,%2,%3};"
        : "+f"(c[0]), "+f"(c[1]), "+f"(c[2]), "+f"(c[3])
        : "r"(a[0]), "r"(a[1]), "r"(a[2]), "r"(a[3]), "r"(b0), "r"(b1));
}
__device__ __forceinline__ void mma16816h(float c[4], const uint32_t a[4], uint32_t b0, uint32_t b1) {
    asm volatile(
        "mma.sync.aligned.m16n8k16.row.col.f32.f16.f16.f32 "
        "{%0,%1,%2,%3}, {%4,%5,%6,%7}, {%8,%9}, {%0,%1,%2,%3};"
        : "+f"(c[0]), "+f"(c[1]), "+f"(c[2]), "+f"(c[3])
        : "r"(a[0]), "r"(a[1]), "r"(a[2]), "r"(a[3]), "r"(b0), "r"(b1));
}
__device__ __host__ __forceinline__ int perm8(int g) {
    return (g < 4) ? (2 * g) : (2 * (g - 4) + 1);
}
#define CP_ASYNC16(dst, src) \
    asm volatile("cp.async.cg.shared.global [%0], [%1], 16;" :: "r"(dst), "l"(src))
#define CP_COMMIT() asm volatile("cp.async.commit_group;")
#define CP_WAIT0()  asm volatile("cp.async.wait_group 0;" ::: "memory")
__device__ __forceinline__ uint32_t sptr(const void* p) {
    return (uint32_t)__cvta_generic_to_shared(p);
}

// =====================================================================
// Prep A: split weights into bf16x2 hi/lo words.
// =====================================================================
__global__ __launch_bounds__(256) void split_w_kernel(
    const float* __restrict__ Wq, const float* __restrict__ Wp)
{
    const int idx = blockIdx.x * 256 + threadIdx.x;
    const int r = idx >> 7, w = idx & 127;
    if (r < OC3) {
        float2 f = *(const float2*)(Wq + (size_t)r * CC + 2 * w);
        uint32_t hi, lo;
        split2(f.x, f.y, hi, lo);
        g_WqPh[r * 128 + w] = hi;
        g_WqPl[r * 128 + w] = lo;
    } else {
        const int rr = r - OC3;
        float2 f = *(const float2*)(Wp + (size_t)rr * CC + 2 * w);
        uint32_t hi, lo;
        split2(f.x, f.y, hi, lo);
        g_WpPh[rr * 128 + w] = hi;
        g_WpPl[rr * 128 + w] = lo;
    }
}

// =====================================================================
// Prep B: transpose X [b][c][n] -> single bf16 pairs along c, [ng][c/2].
// =====================================================================
__global__ __launch_bounds__(256) void split_x_kernel(const float* __restrict__ X)
{
    __shared__ float s[64][65];
    const int b  = blockIdx.z;
    const int c0 = blockIdx.y * 64;
    const int n0 = blockIdx.x * 64;
    const int t  = threadIdx.x;

    #pragma unroll
    for (int j = 0; j < 16; j++) {
        const int idx = j * 256 + t;
        const int r = idx >> 6, col = idx & 63;
        s[r][col] = X[(size_t)b * CC * NN + (size_t)(c0 + r) * NN + n0 + col];
    }
    __syncthreads();
    #pragma unroll
    for (int j = 0; j < 8; j++) {
        const int idx = j * 256 + t;
        const int nl = idx >> 5, w = idx & 31;
        const uint32_t hi = bf2_pack(s[2 * w][nl], s[2 * w + 1][nl]);
        g_XPh[((size_t)b * NN + n0 + nl) * 128 + (c0 >> 1) + w] = hi;
    }
}

// =====================================================================
// Shared GEMM mainloop (128M x 128N CTA, K=256, chunk 32).
// =====================================================================
#define STRD 20
#define STGW (128 * STRD)

#define GEMM_MAINLOOP(AH, AL, BH, M0, N0G)                                          \
    uint32_t* sAh = smw;                                                            \
    uint32_t* sAl = smw + 2 * STGW;                                                 \
    uint32_t* sBh = smw + 4 * STGW;                                                 \
    const int t = threadIdx.x;                                                      \
    const int wid = t >> 5, lane = t & 31;                                          \
    const int gr = lane >> 2, gc = lane & 3;                                        \
    const int wm = wid >> 2, wn = wid & 3;                                          \
    float acc[4][4][4];                                                             \
    _Pragma("unroll")                                                               \
    for (int a = 0; a < 4; a++)                                                     \
        _Pragma("unroll")                                                           \
        for (int bq = 0; bq < 4; bq++)                                              \
            _Pragma("unroll")                                                       \
            for (int k = 0; k < 4; k++) acc[a][bq][k] = 0.0f;                       \
    auto load_stage = [&](int ch, int st) {                                         \
        const int c0w = ch * 16;                                                    \
        _Pragma("unroll")                                                           \
        for (int j = 0; j < 2; j++) {                                               \
            const int idx = j * 256 + t;                                            \
            const int r = idx >> 2, w4 = (idx & 3) << 2;                            \
            const uint32_t soff = (st * STGW + r * STRD + w4) * 4;                  \
            CP_ASYNC16(sptr(sAh) + soff, AH + (size_t)(M0 + r) * 128 + c0w + w4);   \
            CP_ASYNC16(sptr(sAl) + soff, AL + (size_t)(M0 + r) * 128 + c0w + w4);   \
            CP_ASYNC16(sptr(sBh) + soff, BH + (size_t)(N0G + r) * 128 + c0w + w4);  \
        }                                                                           \
    };                                                                              \
    load_stage(0, 0);                                                               \
    CP_COMMIT();                                                                    \
    CP_WAIT0();                                                                     \
    __syncthreads();                                                                \
    _Pragma("unroll 1")                                                             \
    for (int ch = 0; ch < 8; ch++) {                                                \
        const int cur = ch & 1;                                                     \
        if (ch < 7) { load_stage(ch + 1, 1 - cur); CP_COMMIT(); }                   \
        _Pragma("unroll")                                                           \
        for (int ks = 0; ks < 2; ks++) {                                            \
            uint32_t ah[4][4], al[4][4];                                            \
            _Pragma("unroll")                                                       \
            for (int mf = 0; mf < 4; mf++) {                                        \
                const int row = wm * 64 + mf * 16 + gr;                             \
                const int base = cur * STGW + row * STRD + ks * 8 + gc;             \
                ah[mf][0] = sAh[base];                                              \
                ah[mf][1] = sAh[base + 8 * STRD];                                   \
                ah[mf][2] = sAh[base + 4];                                          \
                ah[mf][3] = sAh[base + 8 * STRD + 4];                               \
                al[mf][0] = sAl[base];                                              \
                al[mf][1] = sAl[base + 8 * STRD];                                   \
                al[mf][2] = sAl[base + 4];                                          \
                al[mf][3] = sAl[base + 8 * STRD + 4];                               \
            }                                                                       \
            _Pragma("unroll")                                                       \
            for (int nf = 0; nf < 4; nf++) {                                        \
                const int rowb = wn * 32 + nf * 8 + gr;                             \
                const int bas = cur * STGW + rowb * STRD + ks * 8 + gc;             \
                const uint32_t bh0 = sBh[bas], bh1 = sBh[bas + 4];                  \
                _Pragma("unroll")                                                   \
                for (int mf = 0; mf < 4; mf++) {                                    \
                    mma16816(acc[mf][nf], ah[mf], bh0, bh1);                        \
                    mma16816(acc[mf][nf], al[mf], bh0, bh1);                        \
                }                                                                   \
            }                                                                       \
        }                                                                           \
        if (ch < 7) CP_WAIT0();                                                     \
        __syncthreads();                                                            \
    }

// =====================================================================
// QKV GEMM + layout epilogue (Q/K bf16 pair-permuted along d; V fp16
// pair-permuted along n).
// =====================================================================
__global__ __launch_bounds__(256, 2) void qkv_gemm_kernel(const float* __restrict__ bias)
{
    extern __shared__ uint32_t smw[];
    const int n0g = blockIdx.x * 128;
    const int o0  = blockIdx.y * 128;

    GEMM_MAINLOOP(g_WqPh, g_WqPl, g_XPh, o0, n0g)

    #pragma unroll
    for (int mf = 0; mf < 4; mf++) {
        const int o_r = o0 + wm * 64 + mf * 16 + gr;
        const float b0 = bias[o_r], b1 = bias[o_r + 8];
        #pragma unroll
        for (int nf = 0; nf < 4; nf++) {
            acc[mf][nf][0] += b0; acc[mf][nf][1] += b0;
            acc[mf][nf][2] += b1; acc[mf][nf][3] += b1;
        }
    }

    float* sf = (float*)smw;
    __syncthreads();
    #pragma unroll
    for (int mf = 0; mf < 4; mf++) {
        const int o_l = wm * 64 + mf * 16 + gr;
        #pragma unroll
        for (int nf = 0; nf < 4; nf++) {
            const int n_l = wn * 32 + nf * 8 + 2 * gc;
            sf[o_l * 129 + n_l]           = acc[mf][nf][0];
            sf[o_l * 129 + n_l + 1]       = acc[mf][nf][1];
            sf[(o_l + 8) * 129 + n_l]     = acc[mf][nf][2];
            sf[(o_l + 8) * 129 + n_l + 1] = acc[mf][nf][3];
        }
    }
    __syncthreads();

    if (o0 < 2 * CC) {
        const bool isQ = (o0 < CC);
        const float qscale = isQ ? 0.2550165425423146f : 1.0f;  // 1/sqrt(32)*log2(e)
        uint32_t* dst = isQ ? g_QPh : g_KPh;
        const int dbase = isQ ? o0 : (o0 - CC);
        #pragma unroll 4
        for (int idx = t; idx < 8192; idx += 256) {
            const int nl = idx >> 6, w = idx & 63;
            const int ol = 2 * w;
            const uint32_t hi = bf2_pack(sf[ol * 129 + nl] * qscale,
                                         sf[(ol + 1) * 129 + nl] * qscale);
            const int ng = n0g + nl;
            const int b = (ng >= NN) ? 1 : 0;
            const int n = ng - b * NN;
            const int d = dbase + ol;
            const int wd = (d & 31) >> 1;
            const int wp = (wd & 8) | perm8(wd & 7);
            const size_t off = ((size_t)(b * NH + (d >> 5)) * NN + n) * (HD/2) + wp;
            dst[off] = hi;
        }
    } else {
        const int b = (n0g >= NN) ? 1 : 0;
        const int nb = n0g - b * NN;
        #pragma unroll 4
        for (int idx = t; idx < 8192; idx += 256) {
            const int ol = idx >> 6, w = idx & 63;
            const uint32_t hi = f16x2_pack(sf[ol * 129 + 2 * w], sf[ol * 129 + 2 * w + 1]);
            const int d = (o0 - 2 * CC) + ol;
            const int wp = (w & ~7) | perm8(w & 7);
            const size_t off = ((size_t)(b * NH + (d >> 5)) * HD + (d & 31)) * (NN/2) + (nb >> 1) + wp;
            g_VPh[off] = hi;
        }
    }
}

// =====================================================================
// proj GEMM + bias + residual, direct epilogue.
// =====================================================================
__global__ __launch_bounds__(256, 2) void proj_gemm_kernel(
    const float* __restrict__ X, const float* __restrict__ bp,
    float* __restrict__ out)
{
    extern __shared__ uint32_t smw[];
    const int n0g = blockIdx.x * 128;
    const int c0  = blockIdx.y * 128;

    GEMM_MAINLOOP(g_WpPh, g_WpPl, g_OPh, c0, n0g)

    const int b = (n0g >= NN) ? 1 : 0;
    #pragma unroll
    for (int mf = 0; mf < 4; mf++) {
        const int c_r = c0 + wm * 64 + mf * 16 + gr;
        const float bi0 = bp[c_r], bi1 = bp[c_r + 8];
        #pragma unroll
        for (int nf = 0; nf < 4; nf++) {
            const int ngc = n0g + wn * 32 + nf * 8 + 2 * gc;
            const int n = ngc - b * NN;
            const size_t o0i = (size_t)b * CC * NN + (size_t)c_r * NN + n;
            const size_t o1i = o0i + 8 * NN;
            float2 x0 = *(const float2*)(X + o0i);
            float2 x1 = *(const float2*)(X + o1i);
            *(float2*)(out + o0i) = make_float2(acc[mf][nf][0] + bi0 + x0.x,
                                                acc[mf][nf][1] + bi0 + x0.y);
            *(float2*)(out + o1i) = make_float2(acc[mf][nf][2] + bi1 + x1.x,
                                                acc[mf][nf][3] + bi1 + x1.y);
        }
    }
}

// =====================================================================
// Flash attention, split-KV x2: grid (18 qtiles, 16 bh, 2 splits).
// Each CTA: 18 k-tiles. Linear softmax (no max): partial O (unnormalized
// fp32) and partial l written per split; combine kernel normalizes.
// =====================================================================
#define KS 1536   // 64 rows * 24
#define VS 1280   // 32 rows * 40
#define ONE2H 0x3C003C00u   // f16x2 (1.0, 1.0)

__global__ __launch_bounds__(256, 3) void attn_kernel()
{
    extern __shared__ uint32_t sm[];
    uint32_t* sKh = sm;               // [2][KS]
    uint32_t* sVh = sm + 2 * KS;      // [2][VS]

    const int bh = blockIdx.y;
    const int b  = bh >> 3, h = bh & 7;
    const int q0 = blockIdx.x * 128;
    const int sp = blockIdx.z;
    const int kbase = sp * (NN / NSPLIT);   // 1152
    const int t  = threadIdx.x;
    const int wid = t >> 5, lane = t & 31;
    const int gr = lane >> 2, gc = lane & 3;

    const uint32_t* gKh = g_KPh + (size_t)bh * NN * (HD/2);
    const uint32_t* gVh = g_VPh + (size_t)bh * HD * (NN/2);

    uint32_t aQ[2][4];
    {
        const uint32_t* Qb = g_QPh + ((size_t)bh * NN + q0 + wid * 16) * (HD/2);
        #pragma unroll
        for (int ks = 0; ks < 2; ks++) {
            uint2 lo = *(const uint2*)&Qb[(size_t)gr * (HD/2) + ks * 8 + 2 * gc];
            uint2 hi2 = *(const uint2*)&Qb[(size_t)(gr + 8) * (HD/2) + ks * 8 + 2 * gc];
            aQ[ks][0] = lo.x;  aQ[ks][2] = lo.y;
            aQ[ks][1] = hi2.x; aQ[ks][3] = hi2.y;
        }
    }

    auto load_tile = [&](int k0, int s) {
        {   // K: 64 rows x 16 words
            const int r = t >> 2, chn = (t & 3) << 2;
            const uint32_t* src = gKh + (size_t)(k0 + r) * (HD/2) + chn;
            CP_ASYNC16(sptr(sKh + s * KS + r * 24 + chn), src);
        }
        {   // V: 32 rows x 32 words
            const int r = t >> 3, chn = (t & 7) << 2;
            const uint32_t* src = gVh + (size_t)r * (NN/2) + (k0 >> 1) + chn;
            CP_ASYNC16(sptr(sVh + s * VS + r * 40 + chn), src);
        }
    };

    float lc[4];
    float o[4][4];
    #pragma unroll
    for (int k = 0; k < 4; k++) lc[k] = 0.0f;
    #pragma unroll
    for (int nv = 0; nv < 4; nv++)
        #pragma unroll
        for (int k = 0; k < 4; k++) o[nv][k] = 0.0f;

    load_tile(kbase, 0);
    CP_COMMIT();
    CP_WAIT0();
    __syncthreads();

    #pragma unroll 1
    for (int kt = 0; kt < KT_PER_SPLIT; kt++) {
        const int cur = kt & 1;
        if (kt < KT_PER_SPLIT - 1) { load_tile(kbase + (kt + 1) * 64, 1 - cur); CP_COMMIT(); }

        const uint32_t* Kh = sKh + cur * KS;
        const uint32_t* Vh = sVh + cur * VS;

        #pragma unroll
        for (int j = 0; j < 4; j++) {
            float c0[4] = {0.f, 0.f, 0.f, 0.f};
            float c1[4] = {0.f, 0.f, 0.f, 0.f};
            const int b0 = ((2 * j) * 8 + gr) * 24 + 2 * gc;
            const int b1 = ((2 * j + 1) * 8 + gr) * 24 + 2 * gc;
            #pragma unroll
            for (int ks = 0; ks < 2; ks++) {
                const uint2 k0w = *(const uint2*)&Kh[b0 + ks * 8];
                const uint2 k1w = *(const uint2*)&Kh[b1 + ks * 8];
                mma16816(c0, aQ[ks], k0w.x, k0w.y);
                mma16816(c1, aQ[ks], k1w.x, k1w.y);
            }
            uint32_t pA[4];
            pA[0] = ex2_f16x2(f16x2_pack(c0[0], c0[1]));
            pA[1] = ex2_f16x2(f16x2_pack(c0[2], c0[3]));
            pA[2] = ex2_f16x2(f16x2_pack(c1[0], c1[1]));
            pA[3] = ex2_f16x2(f16x2_pack(c1[2], c1[3]));
            mma16816h(lc, pA, ONE2H, ONE2H);
            #pragma unroll
            for (int nv = 0; nv < 4; nv++) {
                const uint2 vv = *(const uint2*)&Vh[(nv * 8 + gr) * 40 + j * 8 + 2 * gc];
                mma16816h(o[nv], pA, vv.x, vv.y);
            }
        }

        CP_WAIT0();
        __syncthreads();
    }

    // ---- write unnormalized partials ----
    const int n0r = q0 + wid * 16 + gr;                 // local n of row 0
    const size_t ng0 = (size_t)b * NN + n0r;
    const size_t ng1 = ng0 + 8;
    float* Of = g_OPf + (size_t)sp * NG * CC;
    #pragma unroll
    for (int nv = 0; nv < 4; nv++) {
        const int c = h * HD + nv * 8 + 2 * gc;
        *(float2*)(Of + ng0 * CC + c) = make_float2(o[nv][0], o[nv][1]);
        *(float2*)(Of + ng1 * CC + c) = make_float2(o[nv][2], o[nv][3]);
    }
    if (gc == 0) {
        float* Lp = g_Lp + (size_t)sp * NBH * NN;
        Lp[(size_t)bh * NN + n0r]     = lc[0];
        Lp[(size_t)bh * NN + n0r + 8] = lc[2];
    }
}

// =====================================================================
// Combine: sum split partials, normalize, pack bf16 into g_OPh.
// One thread per output word (2 channels). 589824 threads.
// =====================================================================
__global__ __launch_bounds__(256) void combine_kernel()
{
    const int idx = blockIdx.x * 256 + threadIdx.x;   // over NG*128
    const int ng = idx >> 7, w = idx & 127;
    const int c = 2 * w;
    const int b = (ng >= NN) ? 1 : 0;
    const int n = ng - b * NN;
    const int bh = b * NH + (c >> 5);

    const float l = g_Lp[(size_t)bh * NN + n] + g_Lp[(size_t)NBH * NN + (size_t)bh * NN + n];
    const float inv = 1.0f / l;
    float2 o0 = *(const float2*)(g_OPf + (size_t)ng * CC + c);
    float2 o1 = *(const float2*)(g_OPf + (size_t)NG * CC + (size_t)ng * CC + c);
    g_OPh[idx] = bf2_pack((o0.x + o1.x) * inv, (o0.y + o1.y) * inv);
}

// =====================================================================
extern "C" void kernel_launch(void* const* d_in, const int* in_sizes, int n_in,
                              void* d_out, int out_size)
{
    const float* x      = (const float*)d_in[0];
    const float* w_qkv  = (const float*)d_in[1];
    const float* b_qkv  = (const float*)d_in[2];
    const float* w_proj = (const float*)d_in[3];
    const float* b_proj = (const float*)d_in[4];
    float* out = (float*)d_out;

    static bool attr_done = false;
    const int gemm_smem = 128 * 129 * 4;             // 66048 B
    const int attn_smem = (2 * KS + 2 * VS) * 4;     // 22528 B
    if (!attr_done) {
        cudaFuncSetAttribute(qkv_gemm_kernel, cudaFuncAttributeMaxDynamicSharedMemorySize, gemm_smem);
        cudaFuncSetAttribute(proj_gemm_kernel, cudaFuncAttributeMaxDynamicSharedMemorySize, gemm_smem);
        cudaFuncSetAttribute(attn_kernel, cudaFuncAttributeMaxDynamicSharedMemorySize, attn_smem);
        attr_done = true;
    }

    split_w_kernel<<<(OC3 + CC) * 128 / 256, 256>>>(w_qkv, w_proj);
    split_x_kernel<<<dim3(NN / 64, CC / 64, BB), 256>>>(x);
    qkv_gemm_kernel<<<dim3(NG / 128, OC3 / 128), 256, gemm_smem>>>(b_qkv);
    attn_kernel<<<dim3(NN / 128, NBH, NSPLIT), 256, attn_smem>>>();
    combine_kernel<<<NG * 128 / 256, 256>>>();
    proj_gemm_kernel<<<dim3(NG / 128, CC / 128), 256, gemm_smem>>>(x, b_proj, out);
}

// round 17
// speedup vs baseline: 1.0848x; 1.0848x over previous
#include <cuda_runtime.h>
#include <cuda_bf16.h>
#include <cstdint>

#define BB   2
#define CC   256
#define NN   2304
#define OC3  768
#define NH   8
#define HD   32
#define NBH  (BB*NH)
#define NG   (BB*NN)     // 4608 flattened (b,n)

// Pair-permuted layouts everywhere: within each 8-word group, original word g
// maps to position (g<4 ? 2g : 2(g-4)+1) so fragment pairs (g, g+4) are adjacent.
__device__ __align__(16) uint32_t g_QPh[NBH * NN * (HD/2)];  // Q bf16 (pre-scaled) [bh][n][16] permuted
__device__ __align__(16) uint32_t g_XPh[NG * 128];           // X bf16 [ng][c/2] permuted
__device__ __align__(16) uint32_t g_WqPh[OC3 * 128];         // W_qkv split [o][c/2] permuted
__device__ __align__(16) uint32_t g_WqPl[OC3 * 128];
__device__ __align__(16) uint32_t g_WpPh[CC * 128];          // W_proj split [c][c'/2] permuted
__device__ __align__(16) uint32_t g_WpPl[CC * 128];
__device__ __align__(16) uint32_t g_KPh[NBH * NN * (HD/2)];  // K bf16 [bh][n][16] permuted
__device__ __align__(16) uint32_t g_VPh[NBH * HD * (NN/2)];  // V^T fp16 [bh][d][n/2] permuted
__device__ __align__(16) uint32_t g_OPh[NG * 128];           // attn out bf16 [ng][c/2] permuted

// ---------------- helpers ----------------
__device__ __forceinline__ uint32_t bf2_pack(float lo_elem, float hi_elem) {
    uint32_t d;
    asm("cvt.rn.bf16x2.f32 %0, %1, %2;" : "=r"(d) : "f"(hi_elem), "f"(lo_elem));
    return d;
}
__device__ __forceinline__ uint32_t f16x2_pack(float lo_elem, float hi_elem) {
    uint32_t d;
    asm("cvt.rn.f16x2.f32 %0, %1, %2;" : "=r"(d) : "f"(hi_elem), "f"(lo_elem));
    return d;
}
__device__ __forceinline__ uint32_t ex2_f16x2(uint32_t v) {
    uint32_t r;
    asm("ex2.approx.f16x2 %0, %1;" : "=r"(r) : "r"(v));
    return r;
}
__device__ __forceinline__ float2 bf2_unpack(uint32_t v) {
    __nv_bfloat162 h;
    *reinterpret_cast<uint32_t*>(&h) = v;
    return __bfloat1622float2(h);
}
__device__ __forceinline__ void split2(float x, float y, uint32_t& hi, uint32_t& lo) {
    hi = bf2_pack(x, y);
    float2 f = bf2_unpack(hi);
    lo = bf2_pack(x - f.x, y - f.y);
}
__device__ __forceinline__ void mma16816(float c[4], const uint32_t a[4], uint32_t b0, uint32_t b1) {
    asm volatile(
        "mma.sync.aligned.m16n8k16.row.col.f32.bf16.bf16.f32 "
        "{%0,%1,%2,%3}, {%4,%5,%6,%7}, {%8,%9}, {%0,%1,%2,%3};"
        : "+f"(c[0]), "+f"(c[1]), "+f"(c[2]), "+f"(c[3])
        : "r"(a[0]), "r"(a[1]), "r"(a[2]), "r"(a[3]), "r"(b0), "r"(b1));
}
__device__ __forceinline__ void mma16816h(float c[4], const uint32_t a[4], uint32_t b0, uint32_t b1) {
    asm volatile(
        "mma.sync.aligned.m16n8k16.row.col.f32.f16.f16.f32 "
        "{%0,%1,%2,%3}, {%4,%5,%6,%7}, {%8,%9}, {%0,%1,%2,%3};"
        : "+f"(c[0]), "+f"(c[1]), "+f"(c[2]), "+f"(c[3])
        : "r"(a[0]), "r"(a[1]), "r"(a[2]), "r"(a[3]), "r"(b0), "r"(b1));
}
__device__ __host__ __forceinline__ int perm8(int g) {
    return (g < 4) ? (2 * g) : (2 * (g - 4) + 1);
}
#define CP_ASYNC16(dst, src) \
    asm volatile("cp.async.cg.shared.global [%0], [%1], 16;" :: "r"(dst), "l"(src))
#define CP_COMMIT() asm volatile("cp.async.commit_group;")
#define CP_WAIT0()  asm volatile("cp.async.wait_group 0;" ::: "memory")
__device__ __forceinline__ uint32_t sptr(const void* p) {
    return (uint32_t)__cvta_generic_to_shared(p);
}

// =====================================================================
// Fused prep: blocks [0, 512) split weights; blocks [512, 800) transpose X.
// Both write pair-permuted word order.
// =====================================================================
__global__ __launch_bounds__(256) void prep_kernel(
    const float* __restrict__ Wq, const float* __restrict__ Wp,
    const float* __restrict__ X)
{
    const int bid = blockIdx.x;
    const int t = threadIdx.x;

    if (bid < 512) {
        const int idx = bid * 256 + t;
        const int r = idx >> 7, w = idx & 127;
        const int wp = (w & ~7) | perm8(w & 7);
        if (r < OC3) {
            float2 f = *(const float2*)(Wq + (size_t)r * CC + 2 * w);
            uint32_t hi, lo;
            split2(f.x, f.y, hi, lo);
            g_WqPh[r * 128 + wp] = hi;
            g_WqPl[r * 128 + wp] = lo;
        } else {
            const int rr = r - OC3;
            float2 f = *(const float2*)(Wp + (size_t)rr * CC + 2 * w);
            uint32_t hi, lo;
            split2(f.x, f.y, hi, lo);
            g_WpPh[rr * 128 + wp] = hi;
            g_WpPl[rr * 128 + wp] = lo;
        }
    } else {
        __shared__ float s[64][65];
        const int bb = bid - 512;                 // 288 blocks = 36 x 4 x 2
        const int bx = bb % 36;
        const int by = (bb / 36) & 3;
        const int b  = bb / 144;
        const int c0 = by * 64;
        const int n0 = bx * 64;

        #pragma unroll
        for (int j = 0; j < 16; j++) {
            const int idx = j * 256 + t;
            const int r = idx >> 6, col = idx & 63;
            s[r][col] = X[(size_t)b * CC * NN + (size_t)(c0 + r) * NN + n0 + col];
        }
        __syncthreads();
        #pragma unroll
        for (int j = 0; j < 8; j++) {
            const int idx = j * 256 + t;
            const int nl = idx >> 5, w = idx & 31;
            const uint32_t hi = bf2_pack(s[2 * w][nl], s[2 * w + 1][nl]);
            const int ww = (c0 >> 1) + w;
            const int wpm = (ww & ~7) | perm8(ww & 7);
            g_XPh[((size_t)b * NN + n0 + nl) * 128 + wpm] = hi;
        }
    }
}

// =====================================================================
// Shared GEMM mainloop (128M x 128N CTA, K=256, chunk 32), LDS.64 frags.
// Stride 24 words/row (conflict-free LDS.64 phases: r*24 mod 32 = 0,24,16,8).
// =====================================================================
#define STRD 24
#define STGW (128 * STRD)

#define GEMM_MAINLOOP(AH, AL, BH, M0, N0G)                                          \
    uint32_t* sAh = smw;                                                            \
    uint32_t* sAl = smw + 2 * STGW;                                                 \
    uint32_t* sBh = smw + 4 * STGW;                                                 \
    const int t = threadIdx.x;                                                      \
    const int wid = t >> 5, lane = t & 31;                                          \
    const int gr = lane >> 2, gc = lane & 3;                                        \
    const int wm = wid >> 2, wn = wid & 3;                                          \
    float acc[4][4][4];                                                             \
    _Pragma("unroll")                                                               \
    for (int a = 0; a < 4; a++)                                                     \
        _Pragma("unroll")                                                           \
        for (int bq = 0; bq < 4; bq++)                                              \
            _Pragma("unroll")                                                       \
            for (int k = 0; k < 4; k++) acc[a][bq][k] = 0.0f;                       \
    auto load_stage = [&](int ch, int st) {                                         \
        const int c0w = ch * 16;                                                    \
        _Pragma("unroll")                                                           \
        for (int j = 0; j < 2; j++) {                                               \
            const int idx = j * 256 + t;                                            \
            const int r = idx >> 2, w4 = (idx & 3) << 2;                            \
            const uint32_t soff = (st * STGW + r * STRD + w4) * 4;                  \
            CP_ASYNC16(sptr(sAh) + soff, AH + (size_t)(M0 + r) * 128 + c0w + w4);   \
            CP_ASYNC16(sptr(sAl) + soff, AL + (size_t)(M0 + r) * 128 + c0w + w4);   \
            CP_ASYNC16(sptr(sBh) + soff, BH + (size_t)(N0G + r) * 128 + c0w + w4);  \
        }                                                                           \
    };                                                                              \
    load_stage(0, 0);                                                               \
    CP_COMMIT();                                                                    \
    CP_WAIT0();                                                                     \
    __syncthreads();                                                                \
    _Pragma("unroll 1")                                                             \
    for (int ch = 0; ch < 8; ch++) {                                                \
        const int cur = ch & 1;                                                     \
        if (ch < 7) { load_stage(ch + 1, 1 - cur); CP_COMMIT(); }                   \
        _Pragma("unroll")                                                           \
        for (int ks = 0; ks < 2; ks++) {                                            \
            uint32_t ah[4][4], al[4][4];                                            \
            _Pragma("unroll")                                                       \
            for (int mf = 0; mf < 4; mf++) {                                        \
                const int row = wm * 64 + mf * 16 + gr;                             \
                const int base = cur * STGW + row * STRD + ks * 8 + 2 * gc;         \
                const uint2 h0 = *(const uint2*)&sAh[base];                         \
                const uint2 h1 = *(const uint2*)&sAh[base + 8 * STRD];              \
                const uint2 l0 = *(const uint2*)&sAl[base];                         \
                const uint2 l1 = *(const uint2*)&sAl[base + 8 * STRD];              \
                ah[mf][0] = h0.x; ah[mf][2] = h0.y;                                 \
                ah[mf][1] = h1.x; ah[mf][3] = h1.y;                                 \
                al[mf][0] = l0.x; al[mf][2] = l0.y;                                 \
                al[mf][1] = l1.x; al[mf][3] = l1.y;                                 \
            }                                                                       \
            _Pragma("unroll")                                                       \
            for (int nf = 0; nf < 4; nf++) {                                        \
                const int rowb = wn * 32 + nf * 8 + gr;                             \
                const uint2 bb = *(const uint2*)&sBh[cur * STGW + rowb * STRD + ks * 8 + 2 * gc]; \
                _Pragma("unroll")                                                   \
                for (int mf = 0; mf < 4; mf++) {                                    \
                    mma16816(acc[mf][nf], ah[mf], bb.x, bb.y);                      \
                    mma16816(acc[mf][nf], al[mf], bb.x, bb.y);                      \
                }                                                                   \
            }                                                                       \
        }                                                                           \
        if (ch < 7) CP_WAIT0();                                                     \
        __syncthreads();                                                            \
    }

// =====================================================================
// QKV GEMM + layout epilogue (Q/K bf16 permuted along d; V fp16 permuted
// along n).
// =====================================================================
__global__ __launch_bounds__(256, 2) void qkv_gemm_kernel(const float* __restrict__ bias)
{
    extern __shared__ uint32_t smw[];
    const int n0g = blockIdx.x * 128;
    const int o0  = blockIdx.y * 128;

    GEMM_MAINLOOP(g_WqPh, g_WqPl, g_XPh, o0, n0g)

    #pragma unroll
    for (int mf = 0; mf < 4; mf++) {
        const int o_r = o0 + wm * 64 + mf * 16 + gr;
        const float b0 = bias[o_r], b1 = bias[o_r + 8];
        #pragma unroll
        for (int nf = 0; nf < 4; nf++) {
            acc[mf][nf][0] += b0; acc[mf][nf][1] += b0;
            acc[mf][nf][2] += b1; acc[mf][nf][3] += b1;
        }
    }

    float* sf = (float*)smw;
    __syncthreads();
    #pragma unroll
    for (int mf = 0; mf < 4; mf++) {
        const int o_l = wm * 64 + mf * 16 + gr;
        #pragma unroll
        for (int nf = 0; nf < 4; nf++) {
            const int n_l = wn * 32 + nf * 8 + 2 * gc;
            sf[o_l * 129 + n_l]           = acc[mf][nf][0];
            sf[o_l * 129 + n_l + 1]       = acc[mf][nf][1];
            sf[(o_l + 8) * 129 + n_l]     = acc[mf][nf][2];
            sf[(o_l + 8) * 129 + n_l + 1] = acc[mf][nf][3];
        }
    }
    __syncthreads();

    if (o0 < 2 * CC) {
        const bool isQ = (o0 < CC);
        const float qscale = isQ ? 0.2550165425423146f : 1.0f;  // 1/sqrt(32)*log2(e)
        uint32_t* dst = isQ ? g_QPh : g_KPh;
        const int dbase = isQ ? o0 : (o0 - CC);
        #pragma unroll 4
        for (int idx = t; idx < 8192; idx += 256) {
            const int nl = idx >> 6, w = idx & 63;
            const int ol = 2 * w;
            const uint32_t hi = bf2_pack(sf[ol * 129 + nl] * qscale,
                                         sf[(ol + 1) * 129 + nl] * qscale);
            const int ng = n0g + nl;
            const int b = (ng >= NN) ? 1 : 0;
            const int n = ng - b * NN;
            const int d = dbase + ol;
            const int wd = (d & 31) >> 1;
            const int wp = (wd & 8) | perm8(wd & 7);
            const size_t off = ((size_t)(b * NH + (d >> 5)) * NN + n) * (HD/2) + wp;
            dst[off] = hi;
        }
    } else {
        const int b = (n0g >= NN) ? 1 : 0;
        const int nb = n0g - b * NN;
        #pragma unroll 4
        for (int idx = t; idx < 8192; idx += 256) {
            const int ol = idx >> 6, w = idx & 63;
            const uint32_t hi = f16x2_pack(sf[ol * 129 + 2 * w], sf[ol * 129 + 2 * w + 1]);
            const int d = (o0 - 2 * CC) + ol;
            const int wp = (w & ~7) | perm8(w & 7);
            const size_t off = ((size_t)(b * NH + (d >> 5)) * HD + (d & 31)) * (NN/2) + (nb >> 1) + wp;
            g_VPh[off] = hi;
        }
    }
}

// =====================================================================
// proj GEMM + bias + residual, direct epilogue.
// =====================================================================
__global__ __launch_bounds__(256, 2) void proj_gemm_kernel(
    const float* __restrict__ X, const float* __restrict__ bp,
    float* __restrict__ out)
{
    extern __shared__ uint32_t smw[];
    const int n0g = blockIdx.x * 128;
    const int c0  = blockIdx.y * 128;

    GEMM_MAINLOOP(g_WpPh, g_WpPl, g_OPh, c0, n0g)

    const int b = (n0g >= NN) ? 1 : 0;
    #pragma unroll
    for (int mf = 0; mf < 4; mf++) {
        const int c_r = c0 + wm * 64 + mf * 16 + gr;
        const float bi0 = bp[c_r], bi1 = bp[c_r + 8];
        #pragma unroll
        for (int nf = 0; nf < 4; nf++) {
            const int ngc = n0g + wn * 32 + nf * 8 + 2 * gc;
            const int n = ngc - b * NN;
            const size_t o0i = (size_t)b * CC * NN + (size_t)c_r * NN + n;
            const size_t o1i = o0i + 8 * NN;
            float2 x0 = *(const float2*)(X + o0i);
            float2 x1 = *(const float2*)(X + o1i);
            *(float2*)(out + o0i) = make_float2(acc[mf][nf][0] + bi0 + x0.x,
                                                acc[mf][nf][1] + bi0 + x0.y);
            *(float2*)(out + o1i) = make_float2(acc[mf][nf][2] + bi1 + x1.x,
                                                acc[mf][nf][3] + bi1 + x1.y);
        }
    }
}

// =====================================================================
// Flash attention (R15 form): fused per-16-key slice, no max shift,
// LDS.64 frag loads, ones-MMA l, direct finalize (permuted g_OPh write).
// =====================================================================
#define KS 1536   // 64 rows * 24
#define VS 1280   // 32 rows * 40
#define ONE2H 0x3C003C00u   // f16x2 (1.0, 1.0)

__global__ __launch_bounds__(256, 2) void attn_kernel()
{
    extern __shared__ uint32_t sm[];
    uint32_t* sKh = sm;               // [2][KS]
    uint32_t* sVh = sm + 2 * KS;      // [2][VS]

    const int bh = blockIdx.y;
    const int b  = bh >> 3, h = bh & 7;
    const int q0 = blockIdx.x * 128;
    const int t  = threadIdx.x;
    const int wid = t >> 5, lane = t & 31;
    const int gr = lane >> 2, gc = lane & 3;

    const uint32_t* gKh = g_KPh + (size_t)bh * NN * (HD/2);
    const uint32_t* gVh = g_VPh + (size_t)bh * HD * (NN/2);

    uint32_t aQ[2][4];
    {
        const uint32_t* Qb = g_QPh + ((size_t)bh * NN + q0 + wid * 16) * (HD/2);
        #pragma unroll
        for (int ks = 0; ks < 2; ks++) {
            uint2 lo = *(const uint2*)&Qb[(size_t)gr * (HD/2) + ks * 8 + 2 * gc];
            uint2 hi2 = *(const uint2*)&Qb[(size_t)(gr + 8) * (HD/2) + ks * 8 + 2 * gc];
            aQ[ks][0] = lo.x;  aQ[ks][2] = lo.y;
            aQ[ks][1] = hi2.x; aQ[ks][3] = hi2.y;
        }
    }

    auto load_tile = [&](int k0, int s) {
        {   // K: 64 rows x 16 words
            const int r = t >> 2, chn = (t & 3) << 2;
            const uint32_t* src = gKh + (size_t)(k0 + r) * (HD/2) + chn;
            CP_ASYNC16(sptr(sKh + s * KS + r * 24 + chn), src);
        }
        {   // V: 32 rows x 32 words
            const int r = t >> 3, chn = (t & 7) << 2;
            const uint32_t* src = gVh + (size_t)r * (NN/2) + (k0 >> 1) + chn;
            CP_ASYNC16(sptr(sVh + s * VS + r * 40 + chn), src);
        }
    };

    float lc[4];
    float o[4][4];
    #pragma unroll
    for (int k = 0; k < 4; k++) lc[k] = 0.0f;
    #pragma unroll
    for (int nv = 0; nv < 4; nv++)
        #pragma unroll
        for (int k = 0; k < 4; k++) o[nv][k] = 0.0f;

    load_tile(0, 0);
    CP_COMMIT();
    CP_WAIT0();
    __syncthreads();

    #pragma unroll 1
    for (int kt = 0; kt < 36; kt++) {
        const int cur = kt & 1;
        if (kt < 35) { load_tile((kt + 1) * 64, 1 - cur); CP_COMMIT(); }

        const uint32_t* Kh = sKh + cur * KS;
        const uint32_t* Vh = sVh + cur * VS;

        #pragma unroll
        for (int j = 0; j < 4; j++) {
            float c0[4] = {0.f, 0.f, 0.f, 0.f};
            float c1[4] = {0.f, 0.f, 0.f, 0.f};
            const int b0 = ((2 * j) * 8 + gr) * 24 + 2 * gc;
            const int b1 = ((2 * j + 1) * 8 + gr) * 24 + 2 * gc;
            #pragma unroll
            for (int ks = 0; ks < 2; ks++) {
                const uint2 k0w = *(const uint2*)&Kh[b0 + ks * 8];
                const uint2 k1w = *(const uint2*)&Kh[b1 + ks * 8];
                mma16816(c0, aQ[ks], k0w.x, k0w.y);
                mma16816(c1, aQ[ks], k1w.x, k1w.y);
            }
            uint32_t pA[4];
            pA[0] = ex2_f16x2(f16x2_pack(c0[0], c0[1]));
            pA[1] = ex2_f16x2(f16x2_pack(c0[2], c0[3]));
            pA[2] = ex2_f16x2(f16x2_pack(c1[0], c1[1]));
            pA[3] = ex2_f16x2(f16x2_pack(c1[2], c1[3]));
            mma16816h(lc, pA, ONE2H, ONE2H);
            #pragma unroll
            for (int nv = 0; nv < 4; nv++) {
                const uint2 vv = *(const uint2*)&Vh[(nv * 8 + gr) * 40 + j * 8 + 2 * gc];
                mma16816h(o[nv], pA, vv.x, vv.y);
            }
        }

        CP_WAIT0();
        __syncthreads();
    }

    // ---- finalize (permuted g_OPh for the proj GEMM's LDS.64 loads) ----
    const float inv0 = 1.0f / lc[0];
    const float inv1 = 1.0f / lc[2];
    const size_t ng0 = (size_t)b * NN + q0 + wid * 16 + gr;
    const size_t ng1 = ng0 + 8;
    #pragma unroll
    for (int nv = 0; nv < 4; nv++) {
        const int wrd = h * 16 + nv * 4 + gc;
        const int wp = (wrd & ~7) | perm8(wrd & 7);
        g_OPh[ng0 * 128 + wp] = bf2_pack(o[nv][0] * inv0, o[nv][1] * inv0);
        g_OPh[ng1 * 128 + wp] = bf2_pack(o[nv][2] * inv1, o[nv][3] * inv1);
    }
}

// =====================================================================
extern "C" void kernel_launch(void* const* d_in, const int* in_sizes, int n_in,
                              void* d_out, int out_size)
{
    const float* x      = (const float*)d_in[0];
    const float* w_qkv  = (const float*)d_in[1];
    const float* b_qkv  = (const float*)d_in[2];
    const float* w_proj = (const float*)d_in[3];
    const float* b_proj = (const float*)d_in[4];
    float* out = (float*)d_out;

    static bool attr_done = false;
    const int gemm_smem = 6 * STGW * 4;              // 73728 B (> 66048 epi)
    const int attn_smem = (2 * KS + 2 * VS) * 4;     // 22528 B
    if (!attr_done) {
        cudaFuncSetAttribute(qkv_gemm_kernel, cudaFuncAttributeMaxDynamicSharedMemorySize, gemm_smem);
        cudaFuncSetAttribute(proj_gemm_kernel, cudaFuncAttributeMaxDynamicSharedMemorySize, gemm_smem);
        cudaFuncSetAttribute(attn_kernel, cudaFuncAttributeMaxDynamicSharedMemorySize, attn_smem);
        attr_done = true;
    }

    prep_kernel<<<800, 256>>>(w_qkv, w_proj, x);
    qkv_gemm_kernel<<<dim3(NG / 128, OC3 / 128), 256, gemm_smem>>>(b_qkv);
    attn_kernel<<<dim3(NN / 128, NBH), 256, attn_smem>>>();
    proj_gemm_kernel<<<dim3(NG / 128, CC / 128), 256, gemm_smem>>>(x, b_proj, out);
}